// round 5
// baseline (speedup 1.0000x reference)
#include <cuda_runtime.h>
#include <cuda_bf16.h>
#include <cstdint>

#define N_NODES_MAX 50000
#define N_EDGES_C   800000
#define D_IN_C      128
#define H1_C        128
#define H2_C        64
#define H3_C        64
#define NPROTO_C    16   // N_CLASSES * N_PROTO
#define MLP_H_C     8

// ---------------- scratch (static __device__, allocation-free) ----------------
__device__ int    g_deg [N_NODES_MAX];
__device__ float  g_dinv[N_NODES_MAX];
__device__ float  g_S   [(size_t)N_NODES_MAX * 128];  // scaled transform  (h@W)*dinv[row]
__device__ float  g_A   [(size_t)N_NODES_MAX * 128];  // accumulator (init = S for self loop)
__device__ float  g_H   [(size_t)N_NODES_MAX * 128];  // layer activation
__device__ int    g_is64;                             // edge_index/y dtype flag

// ---------------- index dtype detection ----------------
__global__ void detect_idx_kernel(const void* ei, int n) {
    // If data is int64, first 4 values are valid node ids. If int32, the
    // reinterpreted int64 words contain a neighbor id in the high 32 bits
    // (prob of all 4 high-words being 0 is ~(1/n)^4 -> negligible).
    const long long* p = (const long long*)ei;
    bool ok = true;
    #pragma unroll
    for (int i = 0; i < 4; i++) {
        long long v = p[i];
        if (v < 0 || v >= (long long)n) ok = false;
    }
    g_is64 = ok ? 1 : 0;
}

__device__ __forceinline__ int load_idx(const void* p, long long elem) {
    if (g_is64) return (int)((const long long*)p)[elem];
    return ((const int*)p)[elem];
}

// ---------------- degree ----------------
__global__ void init_deg_kernel(int n) {
    int i = blockIdx.x * blockDim.x + threadIdx.x;
    if (i < n) g_deg[i] = 1;  // self loop
}

__global__ void count_deg_kernel(const void* ei, int n_edges) {
    int e = blockIdx.x * blockDim.x + threadIdx.x;
    if (e >= n_edges) return;
    int dst = load_idx(ei, (long long)n_edges + e);
    atomicAdd(&g_deg[dst], 1);
}

__global__ void dinv_kernel(int n) {
    int i = blockIdx.x * blockDim.x + threadIdx.x;
    if (i < n) g_dinv[i] = rsqrtf((float)g_deg[i]);
}

// ---------------- GEMM + row-scale:  S = (Hin @ W) * dinv[row];  A = S ----------------
// W is [KDIM, NDIM] row-major (jax lin: (fan_in, fan_out)).
template<int KDIM, int NDIM>
__global__ void gemm_scale_kernel(const float* __restrict__ Hin,
                                  const float* __restrict__ W,
                                  float* __restrict__ S,
                                  float* __restrict__ A,
                                  int n) {
    constexpr int NG   = NDIM / 4;      // float4 column groups (32 or 16)
    constexpr int ROWS = 256 / NG;      // rows per block (8 or 16)
    constexpr int KC   = 64;            // K chunk

    __shared__ float4 ws[KC][NG];
    __shared__ float  hs[ROWS][KC];

    const int row0 = blockIdx.x * ROWS;
    const int cg   = threadIdx.x % NG;
    const int r    = threadIdx.x / NG;
    const int row  = row0 + r;

    float4 acc = make_float4(0.f, 0.f, 0.f, 0.f);

    for (int kc = 0; kc < KDIM; kc += KC) {
        // load W chunk (KC x NDIM)
        for (int i = threadIdx.x; i < KC * NG; i += 256) {
            int kk = i / NG, c = i % NG;
            ws[kk][c] = ((const float4*)(W + (size_t)(kc + kk) * NDIM))[c];
        }
        // load H rows chunk (ROWS x KC)
        for (int i = threadIdx.x; i < ROWS * (KC / 4); i += 256) {
            int rr = i / (KC / 4), c4 = i % (KC / 4);
            int grow = row0 + rr;
            float4 v = make_float4(0.f, 0.f, 0.f, 0.f);
            if (grow < n)
                v = ((const float4*)(Hin + (size_t)grow * KDIM + kc))[c4];
            ((float4*)hs[rr])[c4] = v;
        }
        __syncthreads();

        #pragma unroll
        for (int k = 0; k < KC; k++) {
            float  a = hs[r][k];
            float4 w = ws[k][cg];
            acc.x += a * w.x;
            acc.y += a * w.y;
            acc.z += a * w.z;
            acc.w += a * w.w;
        }
        __syncthreads();
    }

    if (row < n) {
        float dv = g_dinv[row];
        float4 s = make_float4(acc.x * dv, acc.y * dv, acc.z * dv, acc.w * dv);
        ((float4*)(S + (size_t)row * NDIM))[cg] = s;
        ((float4*)(A + (size_t)row * NDIM))[cg] = s;  // self-loop init
    }
}

// ---------------- edge scatter:  A[dst] += S[src]  (vec4 reduction) ----------------
template<int NDIM>
__global__ void scatter_kernel(const void* __restrict__ ei,
                               const float* __restrict__ S,
                               float* __restrict__ A,
                               int n_edges) {
    constexpr int Q = NDIM / 4;
    long long tid = (long long)blockIdx.x * blockDim.x + threadIdx.x;
    long long e = tid / Q;
    int q = (int)(tid % Q);
    if (e >= n_edges) return;

    int src = load_idx(ei, e);
    int dst = load_idx(ei, (long long)n_edges + e);

    float4 v = ((const float4*)(S + (size_t)src * NDIM))[q];
    float* a = A + (size_t)dst * NDIM + (size_t)q * 4;
    asm volatile("red.global.add.v4.f32 [%0], {%1,%2,%3,%4};"
                 :: "l"(a), "f"(v.x), "f"(v.y), "f"(v.z), "f"(v.w)
                 : "memory");
}

// ---------------- epilogue:  H = relu(dinv[i]*A + b) ----------------
template<int NDIM>
__global__ void relu_epi_kernel(const float* __restrict__ A,
                                const float* __restrict__ b,
                                float* __restrict__ H,
                                int n) {
    long long t = (long long)blockIdx.x * blockDim.x + threadIdx.x;
    long long total = (long long)n * (NDIM / 4);
    if (t >= total) return;
    int i = (int)(t / (NDIM / 4));
    int j4 = (int)(t % (NDIM / 4));
    float dv = g_dinv[i];
    float4 a = ((const float4*)(A + (size_t)i * NDIM))[j4];
    float4 bb = ((const float4*)b)[j4];
    float4 h;
    h.x = fmaxf(dv * a.x + bb.x, 0.f);
    h.y = fmaxf(dv * a.y + bb.y, 0.f);
    h.z = fmaxf(dv * a.z + bb.z, 0.f);
    h.w = fmaxf(dv * a.w + bb.w, 0.f);
    ((float4*)(H + (size_t)i * NDIM))[j4] = h;
}

// ---------------- head: prototype distance -> log sim -> MLP -> sigmoid ----------------
__global__ void final_kernel(const float* __restrict__ H,
                             const void* __restrict__ y,
                             const float* __restrict__ proto,   // [16,64]
                             const float* __restrict__ Wf0,     // [16,8]
                             const float* __restrict__ bf0,     // [8]
                             const float* __restrict__ Wf1,     // [8]
                             const float* __restrict__ bf1,     // [1]
                             float* __restrict__ out,
                             int n) {
    __shared__ float ps[NPROTO_C][H3_C];
    __shared__ float psq[NPROTO_C];
    __shared__ float w0[NPROTO_C][MLP_H_C];
    __shared__ float b0[MLP_H_C];
    __shared__ float w1[MLP_H_C];
    __shared__ float b1s;

    for (int i = threadIdx.x; i < NPROTO_C * H3_C; i += blockDim.x)
        ps[i / H3_C][i % H3_C] = proto[i];
    for (int i = threadIdx.x; i < NPROTO_C * MLP_H_C; i += blockDim.x)
        w0[i / MLP_H_C][i % MLP_H_C] = Wf0[i];
    if (threadIdx.x < MLP_H_C) {
        b0[threadIdx.x] = bf0[threadIdx.x];
        w1[threadIdx.x] = Wf1[threadIdx.x];
    }
    if (threadIdx.x == 0) b1s = bf1[0];
    __syncthreads();
    if (threadIdx.x < NPROTO_C) {
        float s = 0.f;
        for (int j = 0; j < H3_C; j++) s += ps[threadIdx.x][j] * ps[threadIdx.x][j];
        psq[threadIdx.x] = s;
    }
    __syncthreads();

    int i = blockIdx.x * blockDim.x + threadIdx.x;
    if (i >= n) return;

    float dot[NPROTO_C];
    #pragma unroll
    for (int p = 0; p < NPROTO_C; p++) dot[p] = 0.f;
    float hh = 0.f;

    const float4* h4 = (const float4*)(H + (size_t)i * H3_C);
    for (int c = 0; c < H3_C / 4; c++) {
        float4 hv = h4[c];
        hh += hv.x * hv.x + hv.y * hv.y + hv.z * hv.z + hv.w * hv.w;
        #pragma unroll
        for (int p = 0; p < NPROTO_C; p++) {
            dot[p] += hv.x * ps[p][c * 4 + 0] + hv.y * ps[p][c * 4 + 1]
                    + hv.z * ps[p][c * 4 + 2] + hv.w * ps[p][c * 4 + 3];
        }
    }

    float z[MLP_H_C];
    #pragma unroll
    for (int j = 0; j < MLP_H_C; j++) z[j] = b0[j];

    #pragma unroll
    for (int p = 0; p < NPROTO_C; p++) {
        float d2 = fmaxf(hh + psq[p] - 2.f * dot[p], 0.f);
        float sim = logf((d2 + 1.0f) / (d2 + 1e-4f));
        #pragma unroll
        for (int j = 0; j < MLP_H_C; j++) z[j] += sim * w0[p][j];
    }

    float t = b1s;
    #pragma unroll
    for (int j = 0; j < MLP_H_C; j++) {
        float x = z[j];
        float g = 0.5f * x * (1.0f + erff(x * 0.70710678118654752f));  // exact GELU
        t += g * w1[j];
    }
    out[i] = 1.0f / (1.0f + expf(-t));

    // second half of output: y as float
    if (g_is64) out[n + i] = (float)((const long long*)y)[i];
    else        out[n + i] = (float)((const int*)y)[i];
}

// ---------------- launch ----------------
extern "C" void kernel_launch(void* const* d_in, const int* in_sizes, int n_in,
                              void* d_out, int out_size) {
    const float* x     = (const float*)d_in[0];
    const void*  ei    = d_in[1];
    const void*  y     = d_in[2];
    const float* W1    = (const float*)d_in[3];
    const float* b1    = (const float*)d_in[4];
    const float* W2    = (const float*)d_in[5];
    const float* b2    = (const float*)d_in[6];
    const float* W3    = (const float*)d_in[7];
    const float* b3    = (const float*)d_in[8];
    const float* proto = (const float*)d_in[9];
    const float* Wf0   = (const float*)d_in[10];
    const float* bf0   = (const float*)d_in[11];
    const float* Wf1   = (const float*)d_in[12];
    const float* bf1   = (const float*)d_in[13];
    float* out = (float*)d_out;

    const int n  = in_sizes[0] / D_IN_C;     // 50000
    const int ne = in_sizes[1] / 2;          // 800000 (element count / 2)

    float* S = nullptr; float* A = nullptr; float* H = nullptr;
    cudaGetSymbolAddress((void**)&S, g_S);
    cudaGetSymbolAddress((void**)&A, g_A);
    cudaGetSymbolAddress((void**)&H, g_H);

    // dtype detection + degree
    detect_idx_kernel<<<1, 1>>>(ei, n);
    init_deg_kernel<<<(n + 255) / 256, 256>>>(n);
    count_deg_kernel<<<(ne + 255) / 256, 256>>>(ei, ne);
    dinv_kernel<<<(n + 255) / 256, 256>>>(n);

    // ---- layer 1: D_IN=128 -> 128 ----
    {
        constexpr int KD = D_IN_C, ND = H1_C;
        int rows = 256 / (ND / 4);
        gemm_scale_kernel<KD, ND><<<(n + rows - 1) / rows, 256>>>(x, W1, S, A, n);
        long long work = (long long)ne * (ND / 4);
        scatter_kernel<ND><<<(unsigned)((work + 255) / 256), 256>>>(ei, S, A, ne);
        long long etot = (long long)n * (ND / 4);
        relu_epi_kernel<ND><<<(unsigned)((etot + 255) / 256), 256>>>(A, b1, H, n);
    }
    // ---- layer 2: 128 -> 64 ----
    {
        constexpr int KD = H1_C, ND = H2_C;
        int rows = 256 / (ND / 4);
        gemm_scale_kernel<KD, ND><<<(n + rows - 1) / rows, 256>>>(H, W2, S, A, n);
        long long work = (long long)ne * (ND / 4);
        scatter_kernel<ND><<<(unsigned)((work + 255) / 256), 256>>>(ei, S, A, ne);
        long long etot = (long long)n * (ND / 4);
        relu_epi_kernel<ND><<<(unsigned)((etot + 255) / 256), 256>>>(A, b2, H, n);
    }
    // ---- layer 3: 64 -> 64 ----
    {
        constexpr int KD = H2_C, ND = H3_C;
        int rows = 256 / (ND / 4);
        gemm_scale_kernel<KD, ND><<<(n + rows - 1) / rows, 256>>>(H, W3, S, A, n);
        long long work = (long long)ne * (ND / 4);
        scatter_kernel<ND><<<(unsigned)((work + 255) / 256), 256>>>(ei, S, A, ne);
        long long etot = (long long)n * (ND / 4);
        relu_epi_kernel<ND><<<(unsigned)((etot + 255) / 256), 256>>>(A, b3, H, n);
    }

    // ---- head ----
    final_kernel<<<(n + 255) / 256, 256>>>(H, y, proto, Wf0, bf0, Wf1, bf1, out, n);
}

// round 7
// speedup vs baseline: 1.3161x; 1.3161x over previous
#include <cuda_runtime.h>
#include <cuda_bf16.h>
#include <cstdint>

#define N_NODES_MAX 50000
#define N_EDGES_MAX 800000
#define D_IN_C      128
#define H1_C        128
#define H2_C        64
#define H3_C        64
#define NPROTO_C    16
#define MLP_H_C     8

// ---------------- scratch (static __device__, allocation-free) ----------------
__device__ int    g_cnt   [N_NODES_MAX];        // incoming-edge count (no self loop)
__device__ int    g_rowptr[N_NODES_MAX + 1];    // CSR row pointers (by dst)
__device__ int    g_cursor[N_NODES_MAX];        // fill cursors
__device__ int    g_col   [N_EDGES_MAX];        // CSR column (src) indices
__device__ float  g_dinv  [N_NODES_MAX];
__device__ float  g_S     [(size_t)N_NODES_MAX * 128];  // (h@W)*dinv[row]
__device__ float  g_H     [(size_t)N_NODES_MAX * 128];  // layer activation
__device__ int    g_is64;

// ---------------- index dtype detection ----------------
__global__ void detect_idx_kernel(const void* ei, int n) {
    const long long* p = (const long long*)ei;
    bool ok = true;
    #pragma unroll
    for (int i = 0; i < 4; i++) {
        long long v = p[i];
        if (v < 0 || v >= (long long)n) ok = false;
    }
    g_is64 = ok ? 1 : 0;
}

__device__ __forceinline__ int load_idx(const void* p, long long elem) {
    if (g_is64) return (int)((const long long*)p)[elem];
    return ((const int*)p)[elem];
}

// ---------------- CSR build ----------------
__global__ void count_kernel(const void* ei, int n_edges) {
    int e = blockIdx.x * blockDim.x + threadIdx.x;
    if (e >= n_edges) return;
    int dst = load_idx(ei, (long long)n_edges + e);
    atomicAdd(&g_cnt[dst], 1);
}

// single-block exclusive scan over g_cnt -> rowptr/cursor, plus dinv
__global__ void scan_kernel(int n) {
    __shared__ int sh[1024];
    const int t = threadIdx.x;
    const int CH = (n + 1023) / 1024;
    const int base = t * CH;

    int s = 0;
    for (int j = 0; j < CH; j++) {
        int i = base + j;
        if (i < n) s += g_cnt[i];
    }
    sh[t] = s;
    __syncthreads();
    // Hillis-Steele inclusive scan
    for (int d = 1; d < 1024; d <<= 1) {
        int v = (t >= d) ? sh[t - d] : 0;
        __syncthreads();
        sh[t] += v;
        __syncthreads();
    }
    int running = sh[t] - s;  // exclusive offset for this chunk
    for (int j = 0; j < CH; j++) {
        int i = base + j;
        if (i < n) {
            int c = g_cnt[i];
            g_rowptr[i] = running;
            g_cursor[i] = running;
            g_dinv[i]   = rsqrtf((float)(c + 1));  // +1 self loop
            running += c;
        }
    }
    if (t == 1023) g_rowptr[n] = sh[1023];
}

__global__ void fill_kernel(const void* ei, int n_edges) {
    int e = blockIdx.x * blockDim.x + threadIdx.x;
    if (e >= n_edges) return;
    int src = load_idx(ei, e);
    int dst = load_idx(ei, (long long)n_edges + e);
    int pos = atomicAdd(&g_cursor[dst], 1);
    g_col[pos] = src;
}

// ---------------- GEMM + row-scale:  S = (Hin @ W) * dinv[row] ----------------
// Register-blocked: TM x TN per thread. W is [KDIM, NDIM] row-major.
template<int KDIM, int NDIM, int BM, int TM, int TN, int KC, int NTHREADS>
__global__ void __launch_bounds__(NTHREADS)
gemm_scale_kernel(const float* __restrict__ Hin,
                  const float* __restrict__ W,
                  float* __restrict__ S,
                  int n) {
    constexpr int TCOLS = NDIM / TN;
    constexpr int TROWS = BM / TM;
    static_assert(TCOLS * TROWS == NTHREADS, "thread shape");
    constexpr int KCP = KC + 4;   // padded hs row stride (in floats, 16B aligned)

    __shared__ float ws[KC][NDIM];
    __shared__ float hs[BM][KCP];

    const int tc = threadIdx.x % TCOLS;
    const int tr = threadIdx.x / TCOLS;
    const int row0 = blockIdx.x * BM;

    float4 acc[TM][TN / 4];
    #pragma unroll
    for (int m = 0; m < TM; m++)
        #pragma unroll
        for (int u = 0; u < TN / 4; u++)
            acc[m][u] = make_float4(0.f, 0.f, 0.f, 0.f);

    for (int kc = 0; kc < KDIM; kc += KC) {
        // load W chunk (KC x NDIM), coalesced float4
        for (int i = threadIdx.x; i < KC * (NDIM / 4); i += NTHREADS) {
            int kk = i / (NDIM / 4), c = i % (NDIM / 4);
            ((float4*)ws[kk])[c] = ((const float4*)(W + (size_t)(kc + kk) * NDIM))[c];
        }
        // load Hin rows chunk (BM x KC), coalesced float4 per row
        for (int i = threadIdx.x; i < BM * (KC / 4); i += NTHREADS) {
            int rr = i / (KC / 4), c4 = i % (KC / 4);
            int grow = row0 + rr;
            float4 v = make_float4(0.f, 0.f, 0.f, 0.f);
            if (grow < n)
                v = ((const float4*)(Hin + (size_t)grow * KDIM + kc))[c4];
            ((float4*)hs[rr])[c4] = v;
        }
        __syncthreads();

        #pragma unroll
        for (int k = 0; k < KC; k++) {
            float a[TM];
            #pragma unroll
            for (int m = 0; m < TM; m++) a[m] = hs[tr * TM + m][k];
            float4 w[TN / 4];
            #pragma unroll
            for (int u = 0; u < TN / 4; u++)
                w[u] = *(const float4*)&ws[k][tc * TN + u * 4];
            #pragma unroll
            for (int m = 0; m < TM; m++) {
                #pragma unroll
                for (int u = 0; u < TN / 4; u++) {
                    acc[m][u].x += a[m] * w[u].x;
                    acc[m][u].y += a[m] * w[u].y;
                    acc[m][u].z += a[m] * w[u].z;
                    acc[m][u].w += a[m] * w[u].w;
                }
            }
        }
        __syncthreads();
    }

    #pragma unroll
    for (int m = 0; m < TM; m++) {
        int row = row0 + tr * TM + m;
        if (row < n) {
            float dv = g_dinv[row];
            #pragma unroll
            for (int u = 0; u < TN / 4; u++) {
                float4 s = acc[m][u];
                s.x *= dv; s.y *= dv; s.z *= dv; s.w *= dv;
                ((float4*)(S + (size_t)row * NDIM))[tc * (TN / 4) + u] = s;
            }
        }
    }
}

// ---------------- CSR aggregation (+self loop +dinv +bias +relu), fused epilogue ----------------
// One lane-group of G = NDIM/4 lanes per dst row; registers accumulate.
template<int NDIM>
__global__ void agg_kernel(const float* __restrict__ S,
                           const float* __restrict__ b,
                           float* __restrict__ H,
                           int n) {
    constexpr int G = NDIM / 4;            // lanes per row (32 or 16)
    constexpr int RPW = 32 / G;            // rows per warp (1 or 2)
    const int warpId = threadIdx.x / 32;
    const int lane = threadIdx.x % 32;
    const int g = lane % G;
    const int row = (blockIdx.x * (blockDim.x / 32) + warpId) * RPW + lane / G;
    if (row >= n) return;

    const float4* S4 = (const float4*)S;
    float4 acc = __ldg(&S4[(size_t)row * G + g]);   // self loop

    const int start = g_rowptr[row];
    const int end   = g_rowptr[row + 1];

    int j = start;
    for (; j + 1 < end; j += 2) {
        int s0 = __ldg(&g_col[j]);
        int s1 = __ldg(&g_col[j + 1]);
        float4 v0 = __ldg(&S4[(size_t)s0 * G + g]);
        float4 v1 = __ldg(&S4[(size_t)s1 * G + g]);
        acc.x += v0.x + v1.x;
        acc.y += v0.y + v1.y;
        acc.z += v0.z + v1.z;
        acc.w += v0.w + v1.w;
    }
    if (j < end) {
        int s0 = __ldg(&g_col[j]);
        float4 v0 = __ldg(&S4[(size_t)s0 * G + g]);
        acc.x += v0.x; acc.y += v0.y; acc.z += v0.z; acc.w += v0.w;
    }

    float dv = g_dinv[row];
    float4 bb = ((const float4*)b)[g];
    float4 h;
    h.x = fmaxf(dv * acc.x + bb.x, 0.f);
    h.y = fmaxf(dv * acc.y + bb.y, 0.f);
    h.z = fmaxf(dv * acc.z + bb.z, 0.f);
    h.w = fmaxf(dv * acc.w + bb.w, 0.f);
    ((float4*)(H + (size_t)row * NDIM))[g] = h;
}

// ---------------- head: prototype distance -> log sim -> MLP -> sigmoid ----------------
__global__ void final_kernel(const float* __restrict__ H,
                             const void* __restrict__ y,
                             const float* __restrict__ proto,   // [16,64]
                             const float* __restrict__ Wf0,     // [16,8]
                             const float* __restrict__ bf0,     // [8]
                             const float* __restrict__ Wf1,     // [8]
                             const float* __restrict__ bf1,     // [1]
                             float* __restrict__ out,
                             int n) {
    __shared__ float ps[NPROTO_C][H3_C];
    __shared__ float psq[NPROTO_C];
    __shared__ float w0[NPROTO_C][MLP_H_C];
    __shared__ float b0[MLP_H_C];
    __shared__ float w1[MLP_H_C];
    __shared__ float b1s;

    for (int i = threadIdx.x; i < NPROTO_C * H3_C; i += blockDim.x)
        ps[i / H3_C][i % H3_C] = proto[i];
    for (int i = threadIdx.x; i < NPROTO_C * MLP_H_C; i += blockDim.x)
        w0[i / MLP_H_C][i % MLP_H_C] = Wf0[i];
    if (threadIdx.x < MLP_H_C) {
        b0[threadIdx.x] = bf0[threadIdx.x];
        w1[threadIdx.x] = Wf1[threadIdx.x];
    }
    if (threadIdx.x == 0) b1s = bf1[0];
    __syncthreads();
    if (threadIdx.x < NPROTO_C) {
        float s = 0.f;
        for (int j = 0; j < H3_C; j++) s += ps[threadIdx.x][j] * ps[threadIdx.x][j];
        psq[threadIdx.x] = s;
    }
    __syncthreads();

    int i = blockIdx.x * blockDim.x + threadIdx.x;
    if (i >= n) return;

    float dot[NPROTO_C];
    #pragma unroll
    for (int p = 0; p < NPROTO_C; p++) dot[p] = 0.f;
    float hh = 0.f;

    const float4* h4 = (const float4*)(H + (size_t)i * H3_C);
    for (int c = 0; c < H3_C / 4; c++) {
        float4 hv = h4[c];
        hh += hv.x * hv.x + hv.y * hv.y + hv.z * hv.z + hv.w * hv.w;
        #pragma unroll
        for (int p = 0; p < NPROTO_C; p++) {
            dot[p] += hv.x * ps[p][c * 4 + 0] + hv.y * ps[p][c * 4 + 1]
                    + hv.z * ps[p][c * 4 + 2] + hv.w * ps[p][c * 4 + 3];
        }
    }

    float z[MLP_H_C];
    #pragma unroll
    for (int j = 0; j < MLP_H_C; j++) z[j] = b0[j];

    #pragma unroll
    for (int p = 0; p < NPROTO_C; p++) {
        float d2 = fmaxf(hh + psq[p] - 2.f * dot[p], 0.f);
        float sim = logf((d2 + 1.0f) / (d2 + 1e-4f));
        #pragma unroll
        for (int j = 0; j < MLP_H_C; j++) z[j] += sim * w0[p][j];
    }

    float t = b1s;
    #pragma unroll
    for (int j = 0; j < MLP_H_C; j++) {
        float x = z[j];
        float gl = 0.5f * x * (1.0f + erff(x * 0.70710678118654752f));  // exact GELU
        t += gl * w1[j];
    }
    out[i] = 1.0f / (1.0f + expf(-t));

    if (g_is64) out[n + i] = (float)((const long long*)y)[i];
    else        out[n + i] = (float)((const int*)y)[i];
}

// ---------------- launch ----------------
extern "C" void kernel_launch(void* const* d_in, const int* in_sizes, int n_in,
                              void* d_out, int out_size) {
    const float* x     = (const float*)d_in[0];
    const void*  ei    = d_in[1];
    const void*  y     = d_in[2];
    const float* W1    = (const float*)d_in[3];
    const float* b1    = (const float*)d_in[4];
    const float* W2    = (const float*)d_in[5];
    const float* b2    = (const float*)d_in[6];
    const float* W3    = (const float*)d_in[7];
    const float* b3    = (const float*)d_in[8];
    const float* proto = (const float*)d_in[9];
    const float* Wf0   = (const float*)d_in[10];
    const float* bf0   = (const float*)d_in[11];
    const float* Wf1   = (const float*)d_in[12];
    const float* bf1   = (const float*)d_in[13];
    float* out = (float*)d_out;

    const int n  = in_sizes[0] / D_IN_C;
    const int ne = in_sizes[1] / 2;

    float* S = nullptr; float* H = nullptr; int* cnt = nullptr;
    cudaGetSymbolAddress((void**)&S, g_S);
    cudaGetSymbolAddress((void**)&H, g_H);
    cudaGetSymbolAddress((void**)&cnt, g_cnt);

    // ---- CSR build + dinv ----
    cudaMemsetAsync(cnt, 0, (size_t)n * sizeof(int));
    detect_idx_kernel<<<1, 1>>>(ei, n);
    count_kernel<<<(ne + 255) / 256, 256>>>(ei, ne);
    scan_kernel<<<1, 1024>>>(n);
    fill_kernel<<<(ne + 255) / 256, 256>>>(ei, ne);

    // ---- layer 1: 128 -> 128 ----
    {
        constexpr int BM = 128;
        gemm_scale_kernel<D_IN_C, H1_C, BM, 8, 8, 16, 256>
            <<<(n + BM - 1) / BM, 256>>>(x, W1, S, n);
        int rpb = (256 / 32) * (32 / (H1_C / 4));   // rows per block
        agg_kernel<H1_C><<<(n + rpb - 1) / rpb, 256>>>(S, b1, H, n);
    }
    // ---- layer 2: 128 -> 64 ----
    {
        constexpr int BM = 128;
        gemm_scale_kernel<H1_C, H2_C, BM, 8, 8, 16, 128>
            <<<(n + BM - 1) / BM, 128>>>(H, W2, S, n);
        int rpb = (256 / 32) * (32 / (H2_C / 4));
        agg_kernel<H2_C><<<(n + rpb - 1) / rpb, 256>>>(S, b2, H, n);
    }
    // ---- layer 3: 64 -> 64 ----
    {
        constexpr int BM = 128;
        gemm_scale_kernel<H2_C, H3_C, BM, 8, 8, 16, 128>
            <<<(n + BM - 1) / BM, 128>>>(H, W3, S, n);
        int rpb = (256 / 32) * (32 / (H3_C / 4));
        agg_kernel<H3_C><<<(n + rpb - 1) / rpb, 256>>>(S, b3, H, n);
    }

    // ---- head ----
    final_kernel<<<(n + 255) / 256, 256>>>(H, y, proto, Wf0, bf0, Wf1, bf1, out, n);
}

// round 10
// speedup vs baseline: 1.3864x; 1.0535x over previous
#include <cuda_runtime.h>
#include <cuda_bf16.h>
#include <cstdint>

#define N_NODES_MAX 50000
#define N_EDGES_MAX 800000
#define D_IN_C      128
#define H1_C        128
#define H2_C        64
#define H3_C        64
#define NPROTO_C    16
#define MLP_H_C     8

// ---------------- scratch (static __device__, allocation-free) ----------------
__device__ int    g_cnt   [N_NODES_MAX];
__device__ int    g_rowptr[N_NODES_MAX + 1];
__device__ int    g_cursor[N_NODES_MAX];
__device__ int    g_col   [N_EDGES_MAX];
__device__ float  g_dinv  [N_NODES_MAX];
__device__ __align__(16) float g_S[(size_t)N_NODES_MAX * 128];
__device__ __align__(16) float g_H[(size_t)N_NODES_MAX * 128];
__device__ int    g_is64;

// ---------------- index dtype detection ----------------
__global__ void detect_idx_kernel(const void* ei, int n) {
    const long long* p = (const long long*)ei;
    bool ok = true;
    #pragma unroll
    for (int i = 0; i < 4; i++) {
        long long v = p[i];
        if (v < 0 || v >= (long long)n) ok = false;
    }
    g_is64 = ok ? 1 : 0;
}

// ---------------- CSR build (4 edges / thread, vectorized) ----------------
__global__ void count_kernel(const void* ei, int ne) {
    int base = (blockIdx.x * blockDim.x + threadIdx.x) * 4;
    if (base >= ne) return;
    bool vec = (base + 3 < ne) && ((ne & 3) == 0);
    if (g_is64) {
        const long long* p = (const long long*)ei + ne;  // dst array
        if (vec) {
            longlong2 d0 = __ldg((const longlong2*)(p + base));
            longlong2 d1 = __ldg((const longlong2*)(p + base + 2));
            atomicAdd(&g_cnt[(int)d0.x], 1);
            atomicAdd(&g_cnt[(int)d0.y], 1);
            atomicAdd(&g_cnt[(int)d1.x], 1);
            atomicAdd(&g_cnt[(int)d1.y], 1);
        } else {
            for (int j = 0; j < 4 && base + j < ne; j++)
                atomicAdd(&g_cnt[(int)p[base + j]], 1);
        }
    } else {
        const int* p = (const int*)ei + ne;
        if (vec) {
            int4 d = __ldg((const int4*)(p + base));
            atomicAdd(&g_cnt[d.x], 1);
            atomicAdd(&g_cnt[d.y], 1);
            atomicAdd(&g_cnt[d.z], 1);
            atomicAdd(&g_cnt[d.w], 1);
        } else {
            for (int j = 0; j < 4 && base + j < ne; j++)
                atomicAdd(&g_cnt[p[base + j]], 1);
        }
    }
}

// single-block exclusive scan over g_cnt -> rowptr/cursor, plus dinv
__global__ void scan_kernel(int n) {
    __shared__ int sh[1024];
    const int t = threadIdx.x;
    const int CH = (n + 1023) / 1024;
    const int base = t * CH;

    int s = 0;
    for (int j = 0; j < CH; j++) {
        int i = base + j;
        if (i < n) s += g_cnt[i];
    }
    sh[t] = s;
    __syncthreads();
    for (int d = 1; d < 1024; d <<= 1) {
        int v = (t >= d) ? sh[t - d] : 0;
        __syncthreads();
        sh[t] += v;
        __syncthreads();
    }
    int running = sh[t] - s;
    for (int j = 0; j < CH; j++) {
        int i = base + j;
        if (i < n) {
            int c = g_cnt[i];
            g_rowptr[i] = running;
            g_cursor[i] = running;
            g_dinv[i]   = rsqrtf((float)(c + 1));
            running += c;
        }
    }
    if (t == 1023) g_rowptr[n] = sh[1023];
}

__global__ void fill_kernel(const void* ei, int ne) {
    int base = (blockIdx.x * blockDim.x + threadIdx.x) * 4;
    if (base >= ne) return;
    bool vec = (base + 3 < ne) && ((ne & 3) == 0);
    int src[4], dst[4], cnt4 = 4;
    if (g_is64) {
        const long long* ps = (const long long*)ei;
        const long long* pd = ps + ne;
        if (vec) {
            longlong2 s0 = __ldg((const longlong2*)(ps + base));
            longlong2 s1 = __ldg((const longlong2*)(ps + base + 2));
            longlong2 d0 = __ldg((const longlong2*)(pd + base));
            longlong2 d1 = __ldg((const longlong2*)(pd + base + 2));
            src[0]=(int)s0.x; src[1]=(int)s0.y; src[2]=(int)s1.x; src[3]=(int)s1.y;
            dst[0]=(int)d0.x; dst[1]=(int)d0.y; dst[2]=(int)d1.x; dst[3]=(int)d1.y;
        } else {
            cnt4 = 0;
            for (int j = 0; j < 4 && base + j < ne; j++) {
                src[cnt4] = (int)ps[base + j]; dst[cnt4] = (int)pd[base + j]; cnt4++;
            }
        }
    } else {
        const int* ps = (const int*)ei;
        const int* pd = ps + ne;
        if (vec) {
            int4 s = __ldg((const int4*)(ps + base));
            int4 d = __ldg((const int4*)(pd + base));
            src[0]=s.x; src[1]=s.y; src[2]=s.z; src[3]=s.w;
            dst[0]=d.x; dst[1]=d.y; dst[2]=d.z; dst[3]=d.w;
        } else {
            cnt4 = 0;
            for (int j = 0; j < 4 && base + j < ne; j++) {
                src[cnt4] = ps[base + j]; dst[cnt4] = pd[base + j]; cnt4++;
            }
        }
    }
    int pos[4];
    #pragma unroll
    for (int j = 0; j < 4; j++)
        if (j < cnt4) pos[j] = atomicAdd(&g_cursor[dst[j]], 1);
    #pragma unroll
    for (int j = 0; j < 4; j++)
        if (j < cnt4) g_col[pos[j]] = src[j];
}

// ---------------- GEMM + row-scale:  S = (Hin @ W) * dinv[row] ----------------
// Register-blocked 8x8, packed fp32x2 FMA. W is [KDIM, NDIM] row-major.
template<int KDIM, int NDIM, int BM, int KC, int NTHREADS>
__global__ void __launch_bounds__(NTHREADS)
gemm_scale_kernel(const float* __restrict__ Hin,
                  const float* __restrict__ W,
                  float* __restrict__ S,
                  int n) {
    constexpr int TM = 8, TN = 8;
    constexpr int TCOLS = NDIM / TN;
    constexpr int TROWS = BM / TM;
    static_assert(TCOLS * TROWS == NTHREADS, "thread shape");
    constexpr int KCP = KC + 4;   // row stride 144B: keeps float4 stores 16B-aligned

    __shared__ float ws[KC][NDIM];
    __shared__ float hs[BM][KCP];

    const int tc = threadIdx.x % TCOLS;
    const int tr = threadIdx.x / TCOLS;
    const int row0 = blockIdx.x * BM;

    unsigned long long acc[TM][4];
    #pragma unroll
    for (int m = 0; m < TM; m++)
        #pragma unroll
        for (int p = 0; p < 4; p++)
            acc[m][p] = 0ULL;  // packed (0.0f, 0.0f)

    for (int kc = 0; kc < KDIM; kc += KC) {
        for (int i = threadIdx.x; i < KC * (NDIM / 4); i += NTHREADS) {
            int kk = i / (NDIM / 4), c = i % (NDIM / 4);
            ((float4*)ws[kk])[c] = ((const float4*)(W + (size_t)(kc + kk) * NDIM))[c];
        }
        for (int i = threadIdx.x; i < BM * (KC / 4); i += NTHREADS) {
            int rr = i / (KC / 4), c4 = i % (KC / 4);
            int grow = row0 + rr;
            float4 v = make_float4(0.f, 0.f, 0.f, 0.f);
            if (grow < n)
                v = ((const float4*)(Hin + (size_t)grow * KDIM + kc))[c4];
            ((float4*)hs[rr])[c4] = v;   // hs[rr] is 16B-aligned (KCP multiple of 4)
        }
        __syncthreads();

        #pragma unroll 4
        for (int k = 0; k < KC; k++) {
            // w pairs: 4 packed f32x2 operands (columns tc*8 .. tc*8+7)
            ulonglong2 w01 = *(const ulonglong2*)&ws[k][tc * TN];
            ulonglong2 w23 = *(const ulonglong2*)&ws[k][tc * TN + 4];
            // a values (scalar LDS, broadcast-friendly), duplicated into pairs
            unsigned long long ad[TM];
            #pragma unroll
            for (int m = 0; m < TM; m++) {
                float a = hs[tr * TM + m][k];
                asm("mov.b64 %0, {%1, %1};" : "=l"(ad[m]) : "f"(a));
            }
            #pragma unroll
            for (int m = 0; m < TM; m++) {
                asm("fma.rn.f32x2 %0, %1, %2, %0;" : "+l"(acc[m][0]) : "l"(ad[m]), "l"(w01.x));
                asm("fma.rn.f32x2 %0, %1, %2, %0;" : "+l"(acc[m][1]) : "l"(ad[m]), "l"(w01.y));
                asm("fma.rn.f32x2 %0, %1, %2, %0;" : "+l"(acc[m][2]) : "l"(ad[m]), "l"(w23.x));
                asm("fma.rn.f32x2 %0, %1, %2, %0;" : "+l"(acc[m][3]) : "l"(ad[m]), "l"(w23.y));
            }
        }
        __syncthreads();
    }

    #pragma unroll
    for (int m = 0; m < TM; m++) {
        int row = row0 + tr * TM + m;
        if (row < n) {
            float dv = g_dinv[row];
            unsigned long long dvp;
            asm("mov.b64 %0, {%1, %1};" : "=l"(dvp) : "f"(dv));
            unsigned long long r0, r1, r2, r3;
            asm("mul.rn.f32x2 %0, %1, %2;" : "=l"(r0) : "l"(acc[m][0]), "l"(dvp));
            asm("mul.rn.f32x2 %0, %1, %2;" : "=l"(r1) : "l"(acc[m][1]), "l"(dvp));
            asm("mul.rn.f32x2 %0, %1, %2;" : "=l"(r2) : "l"(acc[m][2]), "l"(dvp));
            asm("mul.rn.f32x2 %0, %1, %2;" : "=l"(r3) : "l"(acc[m][3]), "l"(dvp));
            ulonglong2 o0; o0.x = r0; o0.y = r1;
            ulonglong2 o1; o1.x = r2; o1.y = r3;
            *(ulonglong2*)(S + (size_t)row * NDIM + tc * TN)     = o0;  // g_S 16B-aligned
            *(ulonglong2*)(S + (size_t)row * NDIM + tc * TN + 4) = o1;
        }
    }
}

// ---------------- CSR aggregation (+self loop +dinv +bias +relu) ----------------
template<int NDIM>
__global__ void agg_kernel(const float* __restrict__ S,
                           const float* __restrict__ b,
                           float* __restrict__ H,
                           int n) {
    constexpr int G = NDIM / 4;
    constexpr int RPW = 32 / G;
    const int warpId = threadIdx.x / 32;
    const int lane = threadIdx.x % 32;
    const int g = lane % G;
    const int row = (blockIdx.x * (blockDim.x / 32) + warpId) * RPW + lane / G;
    if (row >= n) return;

    const float4* S4 = (const float4*)S;
    float4 acc = __ldg(&S4[(size_t)row * G + g]);   // self loop

    const int start = g_rowptr[row];
    const int end   = g_rowptr[row + 1];

    int j = start;
    for (; j + 3 < end; j += 4) {
        int s0 = __ldg(&g_col[j]);
        int s1 = __ldg(&g_col[j + 1]);
        int s2 = __ldg(&g_col[j + 2]);
        int s3 = __ldg(&g_col[j + 3]);
        float4 v0 = __ldg(&S4[(size_t)s0 * G + g]);
        float4 v1 = __ldg(&S4[(size_t)s1 * G + g]);
        float4 v2 = __ldg(&S4[(size_t)s2 * G + g]);
        float4 v3 = __ldg(&S4[(size_t)s3 * G + g]);
        acc.x += (v0.x + v1.x) + (v2.x + v3.x);
        acc.y += (v0.y + v1.y) + (v2.y + v3.y);
        acc.z += (v0.z + v1.z) + (v2.z + v3.z);
        acc.w += (v0.w + v1.w) + (v2.w + v3.w);
    }
    for (; j < end; j++) {
        int s0 = __ldg(&g_col[j]);
        float4 v0 = __ldg(&S4[(size_t)s0 * G + g]);
        acc.x += v0.x; acc.y += v0.y; acc.z += v0.z; acc.w += v0.w;
    }

    float dv = g_dinv[row];
    float4 bb = ((const float4*)b)[g];
    float4 h;
    h.x = fmaxf(dv * acc.x + bb.x, 0.f);
    h.y = fmaxf(dv * acc.y + bb.y, 0.f);
    h.z = fmaxf(dv * acc.z + bb.z, 0.f);
    h.w = fmaxf(dv * acc.w + bb.w, 0.f);
    ((float4*)(H + (size_t)row * NDIM))[g] = h;
}

// ---------------- head: prototype distance -> log sim -> MLP -> sigmoid ----------------
__global__ void final_kernel(const float* __restrict__ H,
                             const void* __restrict__ y,
                             const float* __restrict__ proto,
                             const float* __restrict__ Wf0,
                             const float* __restrict__ bf0,
                             const float* __restrict__ Wf1,
                             const float* __restrict__ bf1,
                             float* __restrict__ out,
                             int n) {
    __shared__ float ps[NPROTO_C][H3_C];
    __shared__ float psq[NPROTO_C];
    __shared__ float w0[NPROTO_C][MLP_H_C];
    __shared__ float b0[MLP_H_C];
    __shared__ float w1[MLP_H_C];
    __shared__ float b1s;

    for (int i = threadIdx.x; i < NPROTO_C * H3_C; i += blockDim.x)
        ps[i / H3_C][i % H3_C] = proto[i];
    for (int i = threadIdx.x; i < NPROTO_C * MLP_H_C; i += blockDim.x)
        w0[i / MLP_H_C][i % MLP_H_C] = Wf0[i];
    if (threadIdx.x < MLP_H_C) {
        b0[threadIdx.x] = bf0[threadIdx.x];
        w1[threadIdx.x] = Wf1[threadIdx.x];
    }
    if (threadIdx.x == 0) b1s = bf1[0];
    __syncthreads();
    if (threadIdx.x < NPROTO_C) {
        float s = 0.f;
        for (int j = 0; j < H3_C; j++) s += ps[threadIdx.x][j] * ps[threadIdx.x][j];
        psq[threadIdx.x] = s;
    }
    __syncthreads();

    int i = blockIdx.x * blockDim.x + threadIdx.x;
    if (i >= n) return;

    float dot[NPROTO_C];
    #pragma unroll
    for (int p = 0; p < NPROTO_C; p++) dot[p] = 0.f;
    float hh = 0.f;

    const float4* h4 = (const float4*)(H + (size_t)i * H3_C);
    for (int c = 0; c < H3_C / 4; c++) {
        float4 hv = h4[c];
        hh += hv.x * hv.x + hv.y * hv.y + hv.z * hv.z + hv.w * hv.w;
        #pragma unroll
        for (int p = 0; p < NPROTO_C; p++) {
            dot[p] += hv.x * ps[p][c * 4 + 0] + hv.y * ps[p][c * 4 + 1]
                    + hv.z * ps[p][c * 4 + 2] + hv.w * ps[p][c * 4 + 3];
        }
    }

    float z[MLP_H_C];
    #pragma unroll
    for (int j = 0; j < MLP_H_C; j++) z[j] = b0[j];

    #pragma unroll
    for (int p = 0; p < NPROTO_C; p++) {
        float d2 = fmaxf(hh + psq[p] - 2.f * dot[p], 0.f);
        float sim = logf((d2 + 1.0f) / (d2 + 1e-4f));
        #pragma unroll
        for (int j = 0; j < MLP_H_C; j++) z[j] += sim * w0[p][j];
    }

    float t = b1s;
    #pragma unroll
    for (int j = 0; j < MLP_H_C; j++) {
        float x = z[j];
        float gl = 0.5f * x * (1.0f + erff(x * 0.70710678118654752f));
        t += gl * w1[j];
    }
    out[i] = 1.0f / (1.0f + expf(-t));

    if (g_is64) out[n + i] = (float)((const long long*)y)[i];
    else        out[n + i] = (float)((const int*)y)[i];
}

// ---------------- launch ----------------
extern "C" void kernel_launch(void* const* d_in, const int* in_sizes, int n_in,
                              void* d_out, int out_size) {
    const float* x     = (const float*)d_in[0];
    const void*  ei    = d_in[1];
    const void*  y     = d_in[2];
    const float* W1    = (const float*)d_in[3];
    const float* b1    = (const float*)d_in[4];
    const float* W2    = (const float*)d_in[5];
    const float* b2    = (const float*)d_in[6];
    const float* W3    = (const float*)d_in[7];
    const float* b3    = (const float*)d_in[8];
    const float* proto = (const float*)d_in[9];
    const float* Wf0   = (const float*)d_in[10];
    const float* bf0   = (const float*)d_in[11];
    const float* Wf1   = (const float*)d_in[12];
    const float* bf1   = (const float*)d_in[13];
    float* out = (float*)d_out;

    const int n  = in_sizes[0] / D_IN_C;
    const int ne = in_sizes[1] / 2;

    float* S = nullptr; float* H = nullptr; int* cnt = nullptr;
    cudaGetSymbolAddress((void**)&S, g_S);
    cudaGetSymbolAddress((void**)&H, g_H);
    cudaGetSymbolAddress((void**)&cnt, g_cnt);

    // ---- CSR build + dinv ----
    cudaMemsetAsync(cnt, 0, (size_t)n * sizeof(int));
    detect_idx_kernel<<<1, 1>>>(ei, n);
    {
        int nt4 = (ne + 3) / 4;
        count_kernel<<<(nt4 + 255) / 256, 256>>>(ei, ne);
        scan_kernel<<<1, 1024>>>(n);
        fill_kernel<<<(nt4 + 255) / 256, 256>>>(ei, ne);
    }

    // ---- layer 1: 128 -> 128 ----
    {
        constexpr int BM = 128;
        gemm_scale_kernel<D_IN_C, H1_C, BM, 32, 256>
            <<<(n + BM - 1) / BM, 256>>>(x, W1, S, n);
        int rpb = (256 / 32) * (32 / (H1_C / 4));
        agg_kernel<H1_C><<<(n + rpb - 1) / rpb, 256>>>(S, b1, H, n);
    }
    // ---- layer 2: 128 -> 64 ----
    {
        constexpr int BM = 128;
        gemm_scale_kernel<H1_C, H2_C, BM, 32, 128>
            <<<(n + BM - 1) / BM, 128>>>(H, W2, S, n);
        int rpb = (256 / 32) * (32 / (H2_C / 4));
        agg_kernel<H2_C><<<(n + rpb - 1) / rpb, 256>>>(S, b2, H, n);
    }
    // ---- layer 3: 64 -> 64 ----
    {
        constexpr int BM = 128;
        gemm_scale_kernel<H2_C, H3_C, BM, 32, 128>
            <<<(n + BM - 1) / BM, 128>>>(H, W3, S, n);
        int rpb = (256 / 32) * (32 / (H3_C / 4));
        agg_kernel<H3_C><<<(n + rpb - 1) / rpb, 256>>>(S, b3, H, n);
    }

    // ---- head ----
    final_kernel<<<(n + 255) / 256, 256>>>(H, y, proto, Wf0, bf0, Wf1, bf1, out, n);
}